// round 6
// baseline (speedup 1.0000x reference)
#include <cuda_runtime.h>
#include <math.h>

#define Tn   4
#define Bn   32
#define Cn   384
#define HFn  1536
#define HWn  196
#define En   8
#define Nn   128
#define OUT_MAIN (Nn*Cn*HWn)
#define NG   32          // o-groups per expert
#define GSZ  48          // outputs per group
#define NR   12          // channel registers per lane
#define FULLMASK 0xffffffffu

// ---------------- device scratch ----------------
__device__ float g_colmax32[En*Cn*NG];  // [e][c][g] = max_{o in g} w1[e][o][c]
__device__ float g_thrmin32[En*NG];     // per-group conv-domain threshold min (-1e30 = unusable)
__device__ float g_thrall[En];          // min over groups
__device__ float g_maxcm[En];           // max over c of per-channel colmax
__device__ float g_xmin[En];            // exact spike threshold: x >= xmin  <=>  (x/tau - 1) >= 0
__device__ float g_m2c[En*Cn];          // BN2 scale
__device__ float g_a2c[En*Cn];          // BN2 bias fold (b2 included)
__device__ float g_sbar[Nn*Cn];
__device__ int   g_sel[Nn*2];
__device__ float g_gate[Nn*2];
__device__ float g_probs[Nn*En];

// ---------------- prep 1: colmax table ----------------
__global__ void k_colmax32(const float* __restrict__ w1){
  int g = blockIdx.x, e = blockIdx.y, c = threadIdx.x;   // 384 threads
  const float* base = w1 + ((size_t)e*HFn + g*GSZ)*Cn + c;
  float m = -1e30f;
  #pragma unroll 8
  for (int o=0;o<GSZ;o++) m = fmaxf(m, base[(size_t)o*Cn]);
  g_colmax32[((size_t)e*Cn + c)*NG + g] = m;
}

// ---------------- prep 2: thresholds, maxes, BN2 fold, xmin ----------------
__global__ void __launch_bounds__(Cn) k_prep2(
    const float* __restrict__ g1, const float* __restrict__ be1,
    const float* __restrict__ m1, const float* __restrict__ v1,
    const float* __restrict__ b1,
    const float* __restrict__ g2, const float* __restrict__ be2,
    const float* __restrict__ m2, const float* __restrict__ v2,
    const float* __restrict__ b2,
    const float* __restrict__ taus){
  int e = blockIdx.x, tid = threadIdx.x;
  int lane = tid & 31, wid = tid >> 5;
  __shared__ float s_thr[HFn];
  __shared__ float s_red[12];
  float tau = taus[e];

  #pragma unroll
  for (int r=0;r<4;r++){
    int o = tid + r*Cn;
    float iv = g1[e*HFn+o] * rsqrtf(v1[e*HFn+o] + 1e-5f);
    float sh = be1[e*HFn+o] - m1[e*HFn+o]*iv;
    s_thr[o] = (iv > 0.0f) ? ((tau - sh)/iv - b1[e*HFn+o]) : -1e30f;  // conv-domain thr
  }

  // per-channel max over all o, then block max
  const float* p = g_colmax32 + ((size_t)e*Cn + tid)*NG;
  float mx = -1e30f;
  #pragma unroll
  for (int g=0;g<NG;g++) mx = fmaxf(mx, p[g]);
  float wmx = mx;
  #pragma unroll
  for (int d=16;d>=1;d>>=1) wmx = fmaxf(wmx, __shfl_xor_sync(FULLMASK, wmx, d));
  if (lane==0) s_red[wid] = wmx;

  // BN2 fold
  {
    float inv = g2[e*Cn+tid] * rsqrtf(v2[e*Cn+tid] + 1e-5f);
    float sh  = be2[e*Cn+tid] - m2[e*Cn+tid]*inv;
    g_m2c[e*Cn+tid] = inv;
    g_a2c[e*Cn+tid] = inv*b2[e*Cn+tid] + sh;
  }
  __syncthreads();

  if (tid < NG){
    int g = tid;
    float mn = 1e30f;
    #pragma unroll 8
    for (int i=0;i<GSZ;i++) mn = fminf(mn, s_thr[g*GSZ + i]);
    g_thrmin32[e*NG + g] = mn;
    float ta = mn;
    #pragma unroll
    for (int d=16;d>=1;d>>=1) ta = fminf(ta, __shfl_xor_sync(FULLMASK, ta, d));
    if (tid==0) g_thrall[e] = ta;
  }
  if (tid==32){
    float mm = -1e30f;
    #pragma unroll
    for (int w=0;w<12;w++) mm = fmaxf(mm, s_red[w]);
    g_maxcm[e] = mm;
  }
  if (tid==64){
    // smallest float y with (y/tau - 1.0f) >= 0  (identical expression to spike test).
    // Division is monotone in the numerator -> the spike set is {x >= xmin}.
    float y = tau;                    // tau/tau == 1 exactly
    for (int it=0; it<8; it++){
      float z = nextafterf(y, 0.0f);
      if ((z/tau - 1.0f) >= 0.0f) y = z; else break;
    }
    g_xmin[e] = y;
  }
}

// ---------------- router LIF: one warp per (b,c), no block barriers ----------------
__global__ void __launch_bounds__(256) k_lif(const float* __restrict__ x){
  int w = blockIdx.x*8 + (threadIdx.x >> 5);   // 0..12287 = b*Cn + c
  int lane = threadIdx.x & 31;
  int b = w / Cn, c = w - b*Cn;
  const float* xb = x + ((size_t)b*Cn + c)*HWn;
  float v[7] = {0.f,0.f,0.f,0.f,0.f,0.f,0.f};
  #pragma unroll
  for (int t=0;t<Tn;t++){
    const float* xt = xb + (size_t)t*Bn*Cn*HWn;
    int cntl = 0;
    #pragma unroll
    for (int k=0;k<7;k++){
      int p = lane + k*32;
      if (p < HWn){
        float xv = xt[p];
        v[k] += (xv - v[k])*0.5f;
        bool s = (v[k] - 1.0f) >= 0.0f;
        cntl += s ? 1 : 0;
        if (s) v[k] = 0.0f;
      }
    }
    int cnt = __reduce_add_sync(FULLMASK, cntl);
    if (lane==0) g_sbar[(t*Bn+b)*Cn + c] = (float)cnt / (float)HWn;
  }
}

// logits + softmax + top2 + gate, one block per token
__global__ void __launch_bounds__(Cn) k_logits_gate(
    const float* __restrict__ rw, const float* __restrict__ rb,
    const float* __restrict__ rg, const float* __restrict__ rbeta,
    const float* __restrict__ rmean, const float* __restrict__ rvar){
  int n = blockIdx.x, tid = threadIdx.x;
  int lane = tid & 31, wid = tid >> 5;
  __shared__ float s_red[En][13];
  __shared__ float s_lg[En];
  float s = g_sbar[n*Cn + tid];
  #pragma unroll
  for (int e=0;e<En;e++){
    float v = s * rw[e*Cn + tid];
    #pragma unroll
    for (int d=16;d>=1;d>>=1) v += __shfl_xor_sync(FULLMASK, v, d);
    if (lane==0) s_red[e][wid] = v;
  }
  __syncthreads();
  if (tid < En){
    int e = tid;
    float dot = 0.0f;
    #pragma unroll
    for (int w=0;w<12;w++) dot += s_red[e][w];
    float inv = rg[e] * rsqrtf(rvar[e] + 1e-5f);
    s_lg[e] = inv*(dot + rb[e]) + (rbeta[e] - rmean[e]*inv);
  }
  __syncthreads();
  if (tid == 0){
    float lg[En], pe[En];
    float mx = -1e30f;
    #pragma unroll
    for (int e=0;e<En;e++){ lg[e] = s_lg[e]; mx = fmaxf(mx, lg[e]); }
    float sum = 0.0f;
    #pragma unroll
    for (int e=0;e<En;e++){ pe[e] = expf(lg[e]-mx); sum += pe[e]; }
    #pragma unroll
    for (int e=0;e<En;e++){ pe[e] /= sum; g_probs[n*En+e] = pe[e]; }
    int i1 = 0; float p1 = pe[0];
    #pragma unroll
    for (int e=1;e<En;e++) if (pe[e] > p1){ p1 = pe[e]; i1 = e; }
    int i2 = -1; float p2 = -1.0f;
    #pragma unroll
    for (int e=0;e<En;e++) if (e != i1 && pe[e] > p2){ p2 = pe[e]; i2 = e; }
    float ws = p1 + p2;
    g_sel[n*2]   = i1;    g_sel[n*2+1]  = i2;
    g_gate[n*2]  = p1/ws; g_gate[n*2+1] = p2/ws;
  }
}

// ---------------- main expert kernel: one WARP per (token, 7-pixel tile) ----------------
// wu -> token interleaved (wu & 127) to spread heavy (expert-0) warps across SMs.
// Last warp-unit (wu == 3584) computes the aux loss.
__global__ void __launch_bounds__(128) k_expert(
    const float* __restrict__ x, const float* __restrict__ taus,
    const float* __restrict__ w1, const float* __restrict__ b1,
    const float* __restrict__ g1, const float* __restrict__ be1,
    const float* __restrict__ m1, const float* __restrict__ v1,
    const float* __restrict__ w2,
    float* __restrict__ out, float* __restrict__ auxout){
  int wu   = blockIdx.x*4 + (threadIdx.x >> 5);
  int lane = threadIdx.x & 31;

  if (wu >= Nn*28){
    if (wu == Nn*28){
      // aux = 0.01 * E * sum_e f_e * p_e  (warp-local, fixed order)
      float fp = 0.0f;
      #pragma unroll
      for (int e=0;e<En;e++){
        float cntl = 0.0f, pl = 0.0f;
        #pragma unroll
        for (int t=0;t<4;t++){
          int n = lane + t*32;
          int i1 = g_sel[n*2], i2 = g_sel[n*2+1];
          cntl += (i1==e || i2==e) ? 1.0f : 0.0f;
          pl   += g_probs[n*En + e];
        }
        #pragma unroll
        for (int d=16;d>=1;d>>=1){
          cntl += __shfl_xor_sync(FULLMASK, cntl, d);
          pl   += __shfl_xor_sync(FULLMASK, pl, d);
        }
        fp += (cntl/(float)Nn) * (pl/(float)Nn);
      }
      if (lane==0 && auxout) auxout[0] = 0.01f * (float)En * fp;
    }
    return;
  }

  int n  = wu & (Nn-1);
  int p0 = (wu >> 7) * 7;

  int   e0  = g_sel[n*2],   e1  = g_sel[n*2+1];
  float gw0 = g_gate[n*2],  gw1 = g_gate[n*2+1];
  float tau0 = taus[e0],  tau1 = taus[e1];
  float xm0  = g_xmin[e0],  xm1  = g_xmin[e1];
  float thr0 = g_thrall[e0] - 1e-3f, thr1 = g_thrall[e1] - 1e-3f;
  float mc0  = g_maxcm[e0],          mc1  = g_maxcm[e1];

  for (int j=0;j<7;j++){
    int p = p0 + j;
    float xv[NR], res[NR];
    const float* xb = x + ((size_t)n*Cn + lane)*HWn + p;
    #pragma unroll
    for (int r=0;r<NR;r++) xv[r] = xb[(size_t)r*32*HWn];
    #pragma unroll
    for (int r=0;r<NR;r++) res[r] = xv[r] * (gw0 + gw1);   // residual per selected expert

    #pragma unroll
    for (int k=0;k<2;k++){
      int   e   = k ? e1   : e0;
      float gw  = k ? gw1  : gw0;
      float tau = k ? tau1 : tau0;
      float xm  = k ? xm1  : xm0;
      float thr = k ? thr1 : thr0;
      float mc  = k ? mc1  : mc0;
      const float* a2 = g_a2c + e*Cn + lane;

      // ---- layer-1 spikes: lane-local 12-bit mask (exact: x >= xmin <=> x/tau-1 >= 0) ----
      unsigned lm = 0;
      #pragma unroll
      for (int r=0;r<NR;r++) lm |= (xv[r] >= xm) ? (1u << r) : 0u;
      int cnt = __reduce_add_sync(FULLMASK, __popc(lm));

      // ---- tier 0: cnt-only bound ----
      if ((float)cnt * mc < thr){
        #pragma unroll
        for (int r=0;r<NR;r++) res[r] += gw * a2[r*32];
        continue;
      }

      // build per-r warp masks only now
      unsigned msk[NR];
      #pragma unroll
      for (int r=0;r<NR;r++) msk[r] = __ballot_sync(FULLMASK, (lm >> r) & 1u);

      // ---- tier 2: per-group bound; lane = group g (colmax32 rows are L1-resident) ----
      float ub;
      {
        const float* cmB = g_colmax32 + (size_t)e*Cn*NG + lane;
        float pr[4] = {0.f,0.f,0.f,0.f};
        #pragma unroll
        for (int r=0;r<NR;r++){
          unsigned mm = msk[r];
          float pp = 0.0f;
          while (mm){
            int b = __ffs(mm)-1; mm &= mm-1;
            pp += cmB[(size_t)(r*32 + b)*NG];
          }
          pr[r & 3] += pp;
        }
        ub = (pr[0]+pr[1]) + (pr[2]+pr[3]);
      }
      bool fail = ub >= g_thrmin32[e*NG + lane] - 1e-3f;
      unsigned fm = __ballot_sync(FULLMASK, fail);
      if (fm == 0){
        #pragma unroll
        for (int r=0;r<NR;r++) res[r] += gw * a2[r*32];
        continue;
      }

      // ---- tier 3: exact compute for failing groups (rare), warp-local ----
      float a[NR];
      #pragma unroll
      for (int r=0;r<NR;r++) a[r] = 0.0f;
      int nf = 0;
      while (fm){
        int g = __ffs(fm)-1; fm &= fm-1;
        float h0 = 0.0f, h1 = 0.0f;
        const float* w1b = w1 + ((size_t)e*HFn + g*GSZ)*Cn;
        const float* w1r0 = w1b + (size_t)lane*Cn;
        const float* w1r1 = w1b + (size_t)(32+lane)*Cn;
        #pragma unroll
        for (int r=0;r<NR;r++){
          unsigned mm = msk[r];
          while (mm){
            int b = __ffs(mm)-1; mm &= mm-1;
            int c = r*32 + b;
            h0 += w1r0[c];
            if (lane < 16) h1 += w1r1[c];
          }
        }
        int o0 = g*GSZ + lane;
        float iv0 = g1[e*HFn+o0] * rsqrtf(v1[e*HFn+o0] + 1e-5f);
        float q0  = iv0*b1[e*HFn+o0] + (be1[e*HFn+o0] - m1[e*HFn+o0]*iv0) - tau;
        bool f0 = fmaf(iv0, h0, q0) >= 0.0f;
        bool f1 = false;
        if (lane < 16){
          int o1 = g*GSZ + 32 + lane;
          float iv1 = g1[e*HFn+o1] * rsqrtf(v1[e*HFn+o1] + 1e-5f);
          float q1  = iv1*b1[e*HFn+o1] + (be1[e*HFn+o1] - m1[e*HFn+o1]*iv1) - tau;
          f1 = fmaf(iv1, h1, q1) >= 0.0f;
        }
        unsigned fma0 = __ballot_sync(FULLMASK, f0);
        unsigned fma1 = __ballot_sync(FULLMASK, f1);
        unsigned t = fma0;
        while (t){
          int b = __ffs(t)-1; t &= t-1;
          int o = g*GSZ + b;
          const float* w2b = w2 + ((size_t)e*Cn + lane)*HFn + o;
          #pragma unroll
          for (int r=0;r<NR;r++) a[r] += w2b[(size_t)r*32*HFn];
          nf++;
        }
        t = fma1;
        while (t){
          int b = __ffs(t)-1; t &= t-1;
          int o = g*GSZ + 32 + b;
          const float* w2b = w2 + ((size_t)e*Cn + lane)*HFn + o;
          #pragma unroll
          for (int r=0;r<NR;r++) a[r] += w2b[(size_t)r*32*HFn];
          nf++;
        }
      }
      if (nf){
        #pragma unroll
        for (int r=0;r<NR;r++){
          float inv2 = g_m2c[e*Cn + r*32 + lane];
          res[r] += gw * fmaf(inv2, a[r], a2[r*32]);
        }
      } else {
        #pragma unroll
        for (int r=0;r<NR;r++) res[r] += gw * a2[r*32];
      }
    }

    float* ob = out + ((size_t)n*Cn + lane)*HWn + p;
    #pragma unroll
    for (int r=0;r<NR;r++) ob[(size_t)r*32*HWn] = res[r];
  }
}

// ---------------- launch ----------------
extern "C" void kernel_launch(void* const* d_in, const int* in_sizes, int n_in,
                              void* d_out, int out_size){
  const float* x      = (const float*)d_in[0];
  const float* rw     = (const float*)d_in[1];
  const float* rb     = (const float*)d_in[2];
  const float* rgam   = (const float*)d_in[3];
  const float* rbeta  = (const float*)d_in[4];
  const float* rmean  = (const float*)d_in[5];
  const float* rvar   = (const float*)d_in[6];
  const float* w1     = (const float*)d_in[7];
  const float* b1     = (const float*)d_in[8];
  const float* g1     = (const float*)d_in[9];
  const float* be1    = (const float*)d_in[10];
  const float* m1     = (const float*)d_in[11];
  const float* v1     = (const float*)d_in[12];
  const float* w2     = (const float*)d_in[13];
  const float* b2     = (const float*)d_in[14];
  const float* g2     = (const float*)d_in[15];
  const float* be2    = (const float*)d_in[16];
  const float* m2     = (const float*)d_in[17];
  const float* v2     = (const float*)d_in[18];
  const float* taus   = (const float*)d_in[19];
  float* out = (float*)d_out;
  (void)in_sizes; (void)n_in;

  k_colmax32<<<dim3(NG, En), Cn>>>(w1);
  k_prep2<<<En, Cn>>>(g1, be1, m1, v1, b1, g2, be2, m2, v2, b2, taus);
  k_lif<<<(Bn*Cn)/8, 256>>>(x);
  k_logits_gate<<<Nn, Cn>>>(rw, rb, rgam, rbeta, rmean, rvar);
  float* auxp = (out_size > OUT_MAIN) ? (out + OUT_MAIN) : nullptr;
  // 3584 work warp-units + 1 aux warp-unit, 4 warps per 128-thread block
  k_expert<<<(Nn*28 + 4)/4, 128>>>(x, taus, w1, b1, g1, be1, m1, v1, w2, out, auxp);
}

// round 7
// speedup vs baseline: 1.1762x; 1.1762x over previous
#include <cuda_runtime.h>
#include <math.h>

#define Tn   4
#define Bn   32
#define Cn   384
#define HFn  1536
#define HWn  196
#define En   8
#define Nn   128
#define OUT_MAIN (Nn*Cn*HWn)
#define NG   32          // o-groups per expert
#define GSZ  48          // outputs per group
#define NR   12          // channel registers per lane
#define FULLMASK 0xffffffffu

// ---------------- device scratch ----------------
__device__ float g_colmax32[En*Cn*NG];  // [e][c][g] = max_{o in g} w1[e][o][c]
__device__ float g_thrmin32[En*NG];     // per-group conv-domain threshold min (-1e30 = unusable)
__device__ float g_thrall[En];          // min over groups
__device__ float g_maxcm[En];           // max over c of per-channel colmax
__device__ float g_xmin[En];            // exact spike threshold: x >= xmin  <=>  (x/tau - 1) >= 0
__device__ float g_m2c[En*Cn];          // BN2 scale
__device__ float g_a2c[En*Cn];          // BN2 bias fold (b2 included)
__device__ float g_sbar[Nn*Cn];
__device__ int   g_sel[Nn*2];
__device__ float g_gate[Nn*2];
__device__ float g_probs[Nn*En];

// ---------------- prep 1: colmax table ----------------
__global__ void k_colmax32(const float* __restrict__ w1){
  int g = blockIdx.x, e = blockIdx.y, c = threadIdx.x;   // 384 threads
  const float* base = w1 + ((size_t)e*HFn + g*GSZ)*Cn + c;
  float m = -1e30f;
  #pragma unroll 8
  for (int o=0;o<GSZ;o++) m = fmaxf(m, base[(size_t)o*Cn]);
  g_colmax32[((size_t)e*Cn + c)*NG + g] = m;
}

// ---------------- prep 2: thresholds, maxes, BN2 fold, xmin ----------------
__global__ void __launch_bounds__(Cn) k_prep2(
    const float* __restrict__ g1, const float* __restrict__ be1,
    const float* __restrict__ m1, const float* __restrict__ v1,
    const float* __restrict__ b1,
    const float* __restrict__ g2, const float* __restrict__ be2,
    const float* __restrict__ m2, const float* __restrict__ v2,
    const float* __restrict__ b2,
    const float* __restrict__ taus){
  int e = blockIdx.x, tid = threadIdx.x;
  int lane = tid & 31, wid = tid >> 5;
  __shared__ float s_thr[HFn];
  __shared__ float s_red[12];
  float tau = taus[e];

  #pragma unroll
  for (int r=0;r<4;r++){
    int o = tid + r*Cn;
    float iv = g1[e*HFn+o] * rsqrtf(v1[e*HFn+o] + 1e-5f);
    float sh = be1[e*HFn+o] - m1[e*HFn+o]*iv;
    s_thr[o] = (iv > 0.0f) ? ((tau - sh)/iv - b1[e*HFn+o]) : -1e30f;  // conv-domain thr
  }

  // per-channel max over all o, then block max
  const float* p = g_colmax32 + ((size_t)e*Cn + tid)*NG;
  float mx = -1e30f;
  #pragma unroll
  for (int g=0;g<NG;g++) mx = fmaxf(mx, p[g]);
  float wmx = mx;
  #pragma unroll
  for (int d=16;d>=1;d>>=1) wmx = fmaxf(wmx, __shfl_xor_sync(FULLMASK, wmx, d));
  if (lane==0) s_red[wid] = wmx;

  // BN2 fold
  {
    float inv = g2[e*Cn+tid] * rsqrtf(v2[e*Cn+tid] + 1e-5f);
    float sh  = be2[e*Cn+tid] - m2[e*Cn+tid]*inv;
    g_m2c[e*Cn+tid] = inv;
    g_a2c[e*Cn+tid] = inv*b2[e*Cn+tid] + sh;
  }
  __syncthreads();

  if (tid < NG){
    int g = tid;
    float mn = 1e30f;
    #pragma unroll 8
    for (int i=0;i<GSZ;i++) mn = fminf(mn, s_thr[g*GSZ + i]);
    g_thrmin32[e*NG + g] = mn;
    float ta = mn;
    #pragma unroll
    for (int d=16;d>=1;d>>=1) ta = fminf(ta, __shfl_xor_sync(FULLMASK, ta, d));
    if (tid==0) g_thrall[e] = ta;
  }
  if (tid==32){
    float mm = -1e30f;
    #pragma unroll
    for (int w=0;w<12;w++) mm = fmaxf(mm, s_red[w]);
    g_maxcm[e] = mm;
  }
  if (tid==64){
    // smallest float y with (y/tau - 1.0f) >= 0  (same expression as the spike test;
    // division is monotone in the numerator, so the spike set is exactly {x >= xmin})
    float y = tau;                    // tau/tau == 1 exactly
    for (int it=0; it<8; it++){
      float z = nextafterf(y, 0.0f);
      if ((z/tau - 1.0f) >= 0.0f) y = z; else break;
    }
    g_xmin[e] = y;
  }
}

// ---------------- router LIF: one warp per (b,c), no block barriers ----------------
__global__ void __launch_bounds__(256) k_lif(const float* __restrict__ x){
  int w = blockIdx.x*8 + (threadIdx.x >> 5);   // 0..12287 = b*Cn + c
  int lane = threadIdx.x & 31;
  int b = w / Cn, c = w - b*Cn;
  const float* xb = x + ((size_t)b*Cn + c)*HWn;
  float v[7] = {0.f,0.f,0.f,0.f,0.f,0.f,0.f};
  #pragma unroll
  for (int t=0;t<Tn;t++){
    const float* xt = xb + (size_t)t*Bn*Cn*HWn;
    int cntl = 0;
    #pragma unroll
    for (int k=0;k<7;k++){
      int p = lane + k*32;
      if (p < HWn){
        float xv = xt[p];
        v[k] += (xv - v[k])*0.5f;
        bool s = (v[k] - 1.0f) >= 0.0f;
        cntl += s ? 1 : 0;
        if (s) v[k] = 0.0f;
      }
    }
    int cnt = __reduce_add_sync(FULLMASK, cntl);
    if (lane==0) g_sbar[(t*Bn+b)*Cn + c] = (float)cnt / (float)HWn;
  }
}

// logits + softmax + top2 + gate, one block per token
__global__ void __launch_bounds__(Cn) k_logits_gate(
    const float* __restrict__ rw, const float* __restrict__ rb,
    const float* __restrict__ rg, const float* __restrict__ rbeta,
    const float* __restrict__ rmean, const float* __restrict__ rvar){
  int n = blockIdx.x, tid = threadIdx.x;
  int lane = tid & 31, wid = tid >> 5;
  __shared__ float s_red[En][13];
  __shared__ float s_lg[En];
  float s = g_sbar[n*Cn + tid];
  #pragma unroll
  for (int e=0;e<En;e++){
    float v = s * rw[e*Cn + tid];
    #pragma unroll
    for (int d=16;d>=1;d>>=1) v += __shfl_xor_sync(FULLMASK, v, d);
    if (lane==0) s_red[e][wid] = v;
  }
  __syncthreads();
  if (tid < En){
    int e = tid;
    float dot = 0.0f;
    #pragma unroll
    for (int w=0;w<12;w++) dot += s_red[e][w];
    float inv = rg[e] * rsqrtf(rvar[e] + 1e-5f);
    s_lg[e] = inv*(dot + rb[e]) + (rbeta[e] - rmean[e]*inv);
  }
  __syncthreads();
  if (tid == 0){
    float lg[En], pe[En];
    float mx = -1e30f;
    #pragma unroll
    for (int e=0;e<En;e++){ lg[e] = s_lg[e]; mx = fmaxf(mx, lg[e]); }
    float sum = 0.0f;
    #pragma unroll
    for (int e=0;e<En;e++){ pe[e] = expf(lg[e]-mx); sum += pe[e]; }
    #pragma unroll
    for (int e=0;e<En;e++){ pe[e] /= sum; g_probs[n*En+e] = pe[e]; }
    int i1 = 0; float p1 = pe[0];
    #pragma unroll
    for (int e=1;e<En;e++) if (pe[e] > p1){ p1 = pe[e]; i1 = e; }
    int i2 = -1; float p2 = -1.0f;
    #pragma unroll
    for (int e=0;e<En;e++) if (e != i1 && pe[e] > p2){ p2 = pe[e]; i2 = e; }
    float ws = p1 + p2;
    g_sel[n*2]   = i1;    g_sel[n*2+1]  = i2;
    g_gate[n*2]  = p1/ws; g_gate[n*2+1] = p2/ws;
  }
}

// ---------------- main expert kernel: one WARP per (token, 7-pixel tile) ----------------
// Clustered mapping: n = wu/28, so the 8 warps of a block share one token's
// x/out cache lines and the selected experts' colmax tables in L1.
// Warp-unit 3584 (first warp of the extra block) computes the aux loss.
__global__ void __launch_bounds__(256) k_expert(
    const float* __restrict__ x, const float* __restrict__ taus,
    const float* __restrict__ w1, const float* __restrict__ b1,
    const float* __restrict__ g1, const float* __restrict__ be1,
    const float* __restrict__ m1, const float* __restrict__ v1,
    const float* __restrict__ w2,
    float* __restrict__ out, float* __restrict__ auxout){
  int wu   = blockIdx.x*8 + (threadIdx.x >> 5);
  int lane = threadIdx.x & 31;

  if (wu >= Nn*28){
    if (wu == Nn*28){
      // aux = 0.01 * E * sum_e f_e * p_e  (warp-local, fixed order)
      float fp = 0.0f;
      #pragma unroll
      for (int e=0;e<En;e++){
        float cntl = 0.0f, pl = 0.0f;
        #pragma unroll
        for (int t=0;t<4;t++){
          int n = lane + t*32;
          int i1 = g_sel[n*2], i2 = g_sel[n*2+1];
          cntl += (i1==e || i2==e) ? 1.0f : 0.0f;
          pl   += g_probs[n*En + e];
        }
        #pragma unroll
        for (int d=16;d>=1;d>>=1){
          cntl += __shfl_xor_sync(FULLMASK, cntl, d);
          pl   += __shfl_xor_sync(FULLMASK, pl, d);
        }
        fp += (cntl/(float)Nn) * (pl/(float)Nn);
      }
      if (lane==0 && auxout) auxout[0] = 0.01f * (float)En * fp;
    }
    return;
  }

  int n  = wu / 28;
  int p0 = (wu - n*28) * 7;

  int   e0  = g_sel[n*2],   e1  = g_sel[n*2+1];
  float gw0 = g_gate[n*2],  gw1 = g_gate[n*2+1];
  float tau0 = taus[e0],  tau1 = taus[e1];
  float xm0  = g_xmin[e0],  xm1  = g_xmin[e1];
  float thr0 = g_thrall[e0] - 1e-3f, thr1 = g_thrall[e1] - 1e-3f;
  float mc0  = g_maxcm[e0],          mc1  = g_maxcm[e1];

  for (int j=0;j<7;j++){
    int p = p0 + j;
    float xv[NR], res[NR];
    const float* xb = x + ((size_t)n*Cn + lane)*HWn + p;
    #pragma unroll
    for (int r=0;r<NR;r++) xv[r] = xb[(size_t)r*32*HWn];
    #pragma unroll
    for (int r=0;r<NR;r++) res[r] = xv[r] * (gw0 + gw1);   // residual per selected expert

    #pragma unroll
    for (int k=0;k<2;k++){
      int   e   = k ? e1   : e0;
      float gw  = k ? gw1  : gw0;
      float tau = k ? tau1 : tau0;
      float xm  = k ? xm1  : xm0;
      float thr = k ? thr1 : thr0;
      float mc  = k ? mc1  : mc0;
      const float* a2 = g_a2c + e*Cn + lane;

      // ---- layer-1 spikes: lane-local 12-bit mask (exact: x >= xmin <=> x/tau-1 >= 0) ----
      unsigned lm = 0;
      #pragma unroll
      for (int r=0;r<NR;r++) lm |= (xv[r] >= xm) ? (1u << r) : 0u;
      int cnt = __reduce_add_sync(FULLMASK, __popc(lm));

      // ---- tier 0: cnt-only bound ----
      if ((float)cnt * mc < thr){
        #pragma unroll
        for (int r=0;r<NR;r++) res[r] += gw * a2[r*32];
        continue;
      }

      // build per-r warp masks only when tier 0 fails
      unsigned msk[NR];
      #pragma unroll
      for (int r=0;r<NR;r++) msk[r] = __ballot_sync(FULLMASK, (lm >> r) & 1u);

      // ---- tier 2: per-group bound; lane = group g (colmax32 rows L1-resident) ----
      float ub;
      {
        const float* cmB = g_colmax32 + (size_t)e*Cn*NG + lane;
        float pr[4] = {0.f,0.f,0.f,0.f};
        #pragma unroll
        for (int r=0;r<NR;r++){
          unsigned mm = msk[r];
          float pp = 0.0f;
          while (mm){
            int b = __ffs(mm)-1; mm &= mm-1;
            pp += cmB[(size_t)(r*32 + b)*NG];
          }
          pr[r & 3] += pp;
        }
        ub = (pr[0]+pr[1]) + (pr[2]+pr[3]);
      }
      bool fail = ub >= g_thrmin32[e*NG + lane] - 1e-3f;
      unsigned fm = __ballot_sync(FULLMASK, fail);
      if (fm == 0){
        #pragma unroll
        for (int r=0;r<NR;r++) res[r] += gw * a2[r*32];
        continue;
      }

      // ---- tier 3: exact compute for failing groups (rare), warp-local ----
      float a[NR];
      #pragma unroll
      for (int r=0;r<NR;r++) a[r] = 0.0f;
      int nf = 0;
      while (fm){
        int g = __ffs(fm)-1; fm &= fm-1;
        float h0 = 0.0f, h1 = 0.0f;
        const float* w1b = w1 + ((size_t)e*HFn + g*GSZ)*Cn;
        const float* w1r0 = w1b + (size_t)lane*Cn;
        const float* w1r1 = w1b + (size_t)(32+lane)*Cn;
        #pragma unroll
        for (int r=0;r<NR;r++){
          unsigned mm = msk[r];
          while (mm){
            int b = __ffs(mm)-1; mm &= mm-1;
            int c = r*32 + b;
            h0 += w1r0[c];
            if (lane < 16) h1 += w1r1[c];
          }
        }
        int o0 = g*GSZ + lane;
        float iv0 = g1[e*HFn+o0] * rsqrtf(v1[e*HFn+o0] + 1e-5f);
        float q0  = iv0*b1[e*HFn+o0] + (be1[e*HFn+o0] - m1[e*HFn+o0]*iv0) - tau;
        bool f0 = fmaf(iv0, h0, q0) >= 0.0f;
        bool f1 = false;
        if (lane < 16){
          int o1 = g*GSZ + 32 + lane;
          float iv1 = g1[e*HFn+o1] * rsqrtf(v1[e*HFn+o1] + 1e-5f);
          float q1  = iv1*b1[e*HFn+o1] + (be1[e*HFn+o1] - m1[e*HFn+o1]*iv1) - tau;
          f1 = fmaf(iv1, h1, q1) >= 0.0f;
        }
        unsigned fma0 = __ballot_sync(FULLMASK, f0);
        unsigned fma1 = __ballot_sync(FULLMASK, f1);
        unsigned t = fma0;
        while (t){
          int b = __ffs(t)-1; t &= t-1;
          int o = g*GSZ + b;
          const float* w2b = w2 + ((size_t)e*Cn + lane)*HFn + o;
          #pragma unroll
          for (int r=0;r<NR;r++) a[r] += w2b[(size_t)r*32*HFn];
          nf++;
        }
        t = fma1;
        while (t){
          int b = __ffs(t)-1; t &= t-1;
          int o = g*GSZ + 32 + b;
          const float* w2b = w2 + ((size_t)e*Cn + lane)*HFn + o;
          #pragma unroll
          for (int r=0;r<NR;r++) a[r] += w2b[(size_t)r*32*HFn];
          nf++;
        }
      }
      if (nf){
        #pragma unroll
        for (int r=0;r<NR;r++){
          float inv2 = g_m2c[e*Cn + r*32 + lane];
          res[r] += gw * fmaf(inv2, a[r], a2[r*32]);
        }
      } else {
        #pragma unroll
        for (int r=0;r<NR;r++) res[r] += gw * a2[r*32];
      }
    }

    float* ob = out + ((size_t)n*Cn + lane)*HWn + p;
    #pragma unroll
    for (int r=0;r<NR;r++) ob[(size_t)r*32*HWn] = res[r];
  }
}

// ---------------- launch ----------------
extern "C" void kernel_launch(void* const* d_in, const int* in_sizes, int n_in,
                              void* d_out, int out_size){
  const float* x      = (const float*)d_in[0];
  const float* rw     = (const float*)d_in[1];
  const float* rb     = (const float*)d_in[2];
  const float* rgam   = (const float*)d_in[3];
  const float* rbeta  = (const float*)d_in[4];
  const float* rmean  = (const float*)d_in[5];
  const float* rvar   = (const float*)d_in[6];
  const float* w1     = (const float*)d_in[7];
  const float* b1     = (const float*)d_in[8];
  const float* g1     = (const float*)d_in[9];
  const float* be1    = (const float*)d_in[10];
  const float* m1     = (const float*)d_in[11];
  const float* v1     = (const float*)d_in[12];
  const float* w2     = (const float*)d_in[13];
  const float* b2     = (const float*)d_in[14];
  const float* g2     = (const float*)d_in[15];
  const float* be2    = (const float*)d_in[16];
  const float* m2     = (const float*)d_in[17];
  const float* v2     = (const float*)d_in[18];
  const float* taus   = (const float*)d_in[19];
  float* out = (float*)d_out;
  (void)in_sizes; (void)n_in;

  k_colmax32<<<dim3(NG, En), Cn>>>(w1);
  k_prep2<<<En, Cn>>>(g1, be1, m1, v1, b1, g2, be2, m2, v2, b2, taus);
  k_lif<<<(Bn*Cn)/8, 256>>>(x);
  k_logits_gate<<<Nn, Cn>>>(rw, rb, rgam, rbeta, rmean, rvar);
  float* auxp = (out_size > OUT_MAIN) ? (out + OUT_MAIN) : nullptr;
  // 3584 work warp-units + 1 aux warp-unit, 8 warps per 256-thread block
  k_expert<<<(Nn*28 + 8)/8, 256>>>(x, taus, w1, b1, g1, be1, m1, v1, w2, out, auxp);
}

// round 8
// speedup vs baseline: 1.8507x; 1.5735x over previous
#include <cuda_runtime.h>
#include <math.h>

#define Tn   4
#define Bn   32
#define Cn   384
#define HFn  1536
#define HWn  196
#define En   8
#define Nn   128
#define OUT_MAIN (Nn*Cn*HWn)
#define NG   32
#define GSZ  48
#define NR   12
#define FULLMASK 0xffffffffu

#define PB   49                 // pixels per expert block (4 blocks per token)
#define TPB  224                // 7 warps
#define XS_ELEMS (Cn*PB)        // 18816 floats
#define XS_BYTES (XS_ELEMS*4)   // 75264 B

// ---------------- device scratch ----------------
__device__ float    g_colmax32[En*Cn*NG];  // [e][c][g]
__device__ float    g_thrmin32[En*NG];
__device__ float    g_thrall[En];
__device__ unsigned g_maxcm_u[En];         // zero-init; monotone-key atomicMax (idempotent)
__device__ float    g_xmin[En];            // exact: x >= xmin  <=>  (x/tau - 1) >= 0
__device__ float    g_m2c[En*Cn];
__device__ float    g_a2c[En*Cn];
__device__ float    g_sbar[Nn*Cn];

// monotone float<->unsigned key (order-preserving; any finite float key > 0)
__device__ __forceinline__ unsigned fkey(float f){
  unsigned b = __float_as_uint(f);
  return (b & 0x80000000u) ? ~b : (b | 0x80000000u);
}
__device__ __forceinline__ float funkey(unsigned k){
  unsigned b = (k & 0x80000000u) ? (k & 0x7fffffffu) : ~k;
  return __uint_as_float(b);
}

// ============ kernel 1: heterogeneous prep (colmax | thresholds | LIF) ============
__global__ void __launch_bounds__(256) k_prepall(
    const float* __restrict__ x,  const float* __restrict__ w1,
    const float* __restrict__ g1, const float* __restrict__ be1,
    const float* __restrict__ m1, const float* __restrict__ v1,
    const float* __restrict__ b1,
    const float* __restrict__ g2, const float* __restrict__ be2,
    const float* __restrict__ m2, const float* __restrict__ v2,
    const float* __restrict__ b2,
    const float* __restrict__ taus){
  int b = blockIdx.x;
  int tid = threadIdx.x, lane = tid & 31;

  if (b < 256){
    // ---- colmax role: block = (e,g); also atomicMax per-expert maxcm ----
    int e = b >> 5, g = b & 31;
    float lmax = -1e30f;
    for (int c = tid; c < Cn; c += 256){
      const float* base = w1 + ((size_t)e*HFn + g*GSZ)*Cn + c;
      float m = -1e30f;
      #pragma unroll 8
      for (int o=0;o<GSZ;o++) m = fmaxf(m, base[(size_t)o*Cn]);
      g_colmax32[((size_t)e*Cn + c)*NG + g] = m;
      lmax = fmaxf(lmax, m);
    }
    #pragma unroll
    for (int d=16;d>=1;d>>=1) lmax = fmaxf(lmax, __shfl_xor_sync(FULLMASK, lmax, d));
    if (lane==0) atomicMax(&g_maxcm_u[e], fkey(lmax));
    return;
  }

  if (b < 264){
    // ---- prep role: one block per expert ----
    int e = b - 256;
    __shared__ float s_thr[HFn];
    float tau = taus[e];
    for (int o = tid; o < HFn; o += 256){
      float iv = g1[e*HFn+o] * rsqrtf(v1[e*HFn+o] + 1e-5f);
      float sh = be1[e*HFn+o] - m1[e*HFn+o]*iv;
      s_thr[o] = (iv > 0.0f) ? ((tau - sh)/iv - b1[e*HFn+o]) : -1e30f;
    }
    for (int c = tid; c < Cn; c += 256){
      float inv = g2[e*Cn+c] * rsqrtf(v2[e*Cn+c] + 1e-5f);
      float sh  = be2[e*Cn+c] - m2[e*Cn+c]*inv;
      g_m2c[e*Cn+c] = inv;
      g_a2c[e*Cn+c] = inv*b2[e*Cn+c] + sh;
    }
    __syncthreads();
    if (tid < NG){
      float mn = 1e30f;
      #pragma unroll 8
      for (int i=0;i<GSZ;i++) mn = fminf(mn, s_thr[tid*GSZ + i]);
      g_thrmin32[e*NG + tid] = mn;
      float ta = mn;
      #pragma unroll
      for (int d=16;d>=1;d>>=1) ta = fminf(ta, __shfl_xor_sync(FULLMASK, ta, d));
      if (tid==0) g_thrall[e] = ta;
    }
    if (tid==64){
      float y = tau;                       // tau/tau == 1 exactly
      for (int it=0; it<8; it++){
        float z = nextafterf(y, 0.0f);
        if ((z/tau - 1.0f) >= 0.0f) y = z; else break;
      }
      g_xmin[e] = y;
    }
    return;
  }

  // ---- LIF role: one warp per (b,c) ----
  {
    int w = (b - 264)*8 + (tid >> 5);      // 0..12287 = bidx*Cn + c
    int bi = w / Cn, c = w - bi*Cn;
    const float* xb = x + ((size_t)bi*Cn + c)*HWn;
    float v[7] = {0.f,0.f,0.f,0.f,0.f,0.f,0.f};
    #pragma unroll
    for (int t=0;t<Tn;t++){
      const float* xt = xb + (size_t)t*Bn*Cn*HWn;
      int cntl = 0;
      #pragma unroll
      for (int k=0;k<7;k++){
        int p = lane + k*32;
        if (p < HWn){
          float xv = xt[p];
          v[k] += (xv - v[k])*0.5f;
          bool s = (v[k] - 1.0f) >= 0.0f;
          cntl += s ? 1 : 0;
          if (s) v[k] = 0.0f;
        }
      }
      int cnt = __reduce_add_sync(FULLMASK, cntl);
      if (lane==0) g_sbar[(t*Bn+bi)*Cn + c] = (float)cnt / (float)HWn;
    }
  }
}

// ---------------- inline gate: identical code for worker warps and aux ----------------
__device__ __forceinline__ void gate_compute(
    int n, int lane,
    const float* __restrict__ rw, const float* __restrict__ rb,
    const float* __restrict__ rg, const float* __restrict__ rbeta,
    const float* __restrict__ rmean, const float* __restrict__ rvar,
    int& i1o, int& i2o, float& g1o, float& g2o, float* probs){
  float sv[NR];
  #pragma unroll
  for (int r=0;r<NR;r++) sv[r] = g_sbar[n*Cn + r*32 + lane];
  float lg[En];
  #pragma unroll
  for (int e=0;e<En;e++){
    float v = 0.0f;
    #pragma unroll
    for (int r=0;r<NR;r++) v += sv[r] * rw[e*Cn + r*32 + lane];
    #pragma unroll
    for (int d=16;d>=1;d>>=1) v += __shfl_xor_sync(FULLMASK, v, d);
    float inv = rg[e] * rsqrtf(rvar[e] + 1e-5f);
    lg[e] = inv*(v + rb[e]) + (rbeta[e] - rmean[e]*inv);
  }
  float mx = lg[0];
  #pragma unroll
  for (int e=1;e<En;e++) mx = fmaxf(mx, lg[e]);
  float pe[En]; float sum = 0.0f;
  #pragma unroll
  for (int e=0;e<En;e++){ pe[e] = expf(lg[e]-mx); sum += pe[e]; }
  #pragma unroll
  for (int e=0;e<En;e++) pe[e] /= sum;
  int i1 = 0; float p1 = pe[0];
  #pragma unroll
  for (int e=1;e<En;e++) if (pe[e] > p1){ p1 = pe[e]; i1 = e; }
  int i2 = -1; float p2 = -1.0f;
  #pragma unroll
  for (int e=0;e<En;e++) if (e != i1 && pe[e] > p2){ p2 = pe[e]; i2 = e; }
  float ws = p1 + p2;
  i1o = i1; i2o = i2; g1o = p1/ws; g2o = p2/ws;
  if (probs){
    #pragma unroll
    for (int e=0;e<En;e++) probs[e] = pe[e];
  }
}

// ============ kernel 2: expert (smem-staged) + aux block ============
extern __shared__ float xs[];   // [Cn][PB]

__global__ void __launch_bounds__(TPB) k_expert(
    const float* __restrict__ x,
    const float* __restrict__ rw, const float* __restrict__ rb,
    const float* __restrict__ rg, const float* __restrict__ rbeta,
    const float* __restrict__ rmean, const float* __restrict__ rvar,
    const float* __restrict__ taus,
    const float* __restrict__ w1, const float* __restrict__ b1,
    const float* __restrict__ g1, const float* __restrict__ be1,
    const float* __restrict__ m1, const float* __restrict__ v1,
    const float* __restrict__ w2,
    float* __restrict__ out, float* __restrict__ auxout){
  int b = blockIdx.x;
  int tid = threadIdx.x, lane = tid & 31, w = tid >> 5;

  if (b >= Nn*4){
    // ---- aux block: same gate code -> identical selection ----
    float* fs = xs;        // [7][8]
    float* ps = xs + 64;   // [7][8]
    float facc[En], pacc[En];
    #pragma unroll
    for (int e=0;e<En;e++){ facc[e]=0.f; pacc[e]=0.f; }
    for (int n = w; n < Nn; n += 7){
      int i1,i2; float a,bb; float pe[En];
      gate_compute(n, lane, rw, rb, rg, rbeta, rmean, rvar, i1, i2, a, bb, pe);
      #pragma unroll
      for (int e=0;e<En;e++){
        facc[e] += (i1==e || i2==e) ? 1.0f : 0.0f;
        pacc[e] += pe[e];
      }
    }
    if (lane==0){
      #pragma unroll
      for (int e=0;e<En;e++){ fs[w*8+e] = facc[e]; ps[w*8+e] = pacc[e]; }
    }
    __syncthreads();
    if (tid==0 && auxout){
      float s = 0.0f;
      #pragma unroll
      for (int e=0;e<En;e++){
        float fe = 0.f, pp = 0.f;
        #pragma unroll
        for (int q=0;q<7;q++){ fe += fs[q*8+e]; pp += ps[q*8+e]; }
        s += (fe/(float)Nn) * (pp/(float)Nn);
      }
      auxout[0] = 0.01f * (float)En * s;
    }
    return;
  }

  int n = b >> 2;
  int pbase = (b & 3) * PB;

  // ---- cooperative coalesced load of the x tile [384][49] ----
  const float* xrow = x + (size_t)n*Cn*HWn + pbase;
  for (int i = tid; i < XS_ELEMS; i += TPB){
    int c = i / PB, p = i - c*PB;
    xs[i] = xrow[(size_t)c*HWn + p];
  }

  // ---- per-warp gate (global reads; overlaps the pending loads) ----
  int e0, e1; float gw0, gw1;
  gate_compute(n, lane, rw, rb, rg, rbeta, rmean, rvar, e0, e1, gw0, gw1, (float*)0);

  float tau0 = taus[e0],  tau1 = taus[e1];
  float xm0  = g_xmin[e0], xm1 = g_xmin[e1];
  float thr0 = g_thrall[e0] - 1e-3f, thr1 = g_thrall[e1] - 1e-3f;
  float mc0  = funkey(g_maxcm_u[e0]), mc1 = funkey(g_maxcm_u[e1]);

  __syncthreads();

  // ---- compute: warp w owns smem columns 7w..7w+6 (no further barriers until the end) ----
  for (int j=0;j<7;j++){
    int col = w*7 + j;
    float xv[NR], res[NR];
    #pragma unroll
    for (int r=0;r<NR;r++) xv[r] = xs[(r*32+lane)*PB + col];
    #pragma unroll
    for (int r=0;r<NR;r++) res[r] = xv[r] * (gw0 + gw1);

    #pragma unroll
    for (int k=0;k<2;k++){
      int   e   = k ? e1   : e0;
      float gw  = k ? gw1  : gw0;
      float tau = k ? tau1 : tau0;
      float xm  = k ? xm1  : xm0;
      float thr = k ? thr1 : thr0;
      float mc  = k ? mc1  : mc0;
      const float* a2 = g_a2c + e*Cn + lane;

      unsigned lm = 0;
      #pragma unroll
      for (int r=0;r<NR;r++) lm |= (xv[r] >= xm) ? (1u << r) : 0u;
      int cnt = __reduce_add_sync(FULLMASK, __popc(lm));

      if ((float)cnt * mc < thr){
        #pragma unroll
        for (int r=0;r<NR;r++) res[r] += gw * a2[r*32];
        continue;
      }

      unsigned msk[NR];
      #pragma unroll
      for (int r=0;r<NR;r++) msk[r] = __ballot_sync(FULLMASK, (lm >> r) & 1u);

      float ub;
      {
        const float* cmB = g_colmax32 + (size_t)e*Cn*NG + lane;
        float pr[4] = {0.f,0.f,0.f,0.f};
        #pragma unroll
        for (int r=0;r<NR;r++){
          unsigned mm = msk[r];
          float pp = 0.0f;
          while (mm){
            int bb = __ffs(mm)-1; mm &= mm-1;
            pp += cmB[(size_t)(r*32 + bb)*NG];
          }
          pr[r & 3] += pp;
        }
        ub = (pr[0]+pr[1]) + (pr[2]+pr[3]);
      }
      bool fail = ub >= g_thrmin32[e*NG + lane] - 1e-3f;
      unsigned fm = __ballot_sync(FULLMASK, fail);
      if (fm == 0){
        #pragma unroll
        for (int r=0;r<NR;r++) res[r] += gw * a2[r*32];
        continue;
      }

      // tier 3: exact for failing groups (rare)
      float a[NR];
      #pragma unroll
      for (int r=0;r<NR;r++) a[r] = 0.0f;
      int nf = 0;
      while (fm){
        int g = __ffs(fm)-1; fm &= fm-1;
        float h0 = 0.0f, h1 = 0.0f;
        const float* w1b  = w1 + ((size_t)e*HFn + g*GSZ)*Cn;
        const float* w1r0 = w1b + (size_t)lane*Cn;
        const float* w1r1 = w1b + (size_t)(32+lane)*Cn;
        #pragma unroll
        for (int r=0;r<NR;r++){
          unsigned mm = msk[r];
          while (mm){
            int bb = __ffs(mm)-1; mm &= mm-1;
            int c = r*32 + bb;
            h0 += w1r0[c];
            if (lane < 16) h1 += w1r1[c];
          }
        }
        int o0 = g*GSZ + lane;
        float iv0 = g1[e*HFn+o0] * rsqrtf(v1[e*HFn+o0] + 1e-5f);
        float q0  = iv0*b1[e*HFn+o0] + (be1[e*HFn+o0] - m1[e*HFn+o0]*iv0) - tau;
        bool f0 = fmaf(iv0, h0, q0) >= 0.0f;
        bool f1 = false;
        if (lane < 16){
          int o1 = g*GSZ + 32 + lane;
          float iv1 = g1[e*HFn+o1] * rsqrtf(v1[e*HFn+o1] + 1e-5f);
          float q1  = iv1*b1[e*HFn+o1] + (be1[e*HFn+o1] - m1[e*HFn+o1]*iv1) - tau;
          f1 = fmaf(iv1, h1, q1) >= 0.0f;
        }
        unsigned fa0 = __ballot_sync(FULLMASK, f0);
        unsigned fa1 = __ballot_sync(FULLMASK, f1);
        unsigned t = fa0;
        while (t){
          int bb = __ffs(t)-1; t &= t-1;
          const float* w2b = w2 + ((size_t)e*Cn + lane)*HFn + (g*GSZ + bb);
          #pragma unroll
          for (int r=0;r<NR;r++) a[r] += w2b[(size_t)r*32*HFn];
          nf++;
        }
        t = fa1;
        while (t){
          int bb = __ffs(t)-1; t &= t-1;
          const float* w2b = w2 + ((size_t)e*Cn + lane)*HFn + (g*GSZ + 32 + bb);
          #pragma unroll
          for (int r=0;r<NR;r++) a[r] += w2b[(size_t)r*32*HFn];
          nf++;
        }
      }
      if (nf){
        #pragma unroll
        for (int r=0;r<NR;r++){
          float inv2 = g_m2c[e*Cn + r*32 + lane];
          res[r] += gw * fmaf(inv2, a[r], a2[r*32]);
        }
      } else {
        #pragma unroll
        for (int r=0;r<NR;r++) res[r] += gw * a2[r*32];
      }
    }

    #pragma unroll
    for (int r=0;r<NR;r++) xs[(r*32+lane)*PB + col] = res[r];
  }

  __syncthreads();

  // ---- cooperative coalesced store ----
  float* orow = out + (size_t)n*Cn*HWn + pbase;
  for (int i = tid; i < XS_ELEMS; i += TPB){
    int c = i / PB, p = i - c*PB;
    orow[(size_t)c*HWn + p] = xs[i];
  }
}

// ---------------- launch ----------------
extern "C" void kernel_launch(void* const* d_in, const int* in_sizes, int n_in,
                              void* d_out, int out_size){
  const float* x      = (const float*)d_in[0];
  const float* rw     = (const float*)d_in[1];
  const float* rb     = (const float*)d_in[2];
  const float* rgam   = (const float*)d_in[3];
  const float* rbeta  = (const float*)d_in[4];
  const float* rmean  = (const float*)d_in[5];
  const float* rvar   = (const float*)d_in[6];
  const float* w1     = (const float*)d_in[7];
  const float* b1     = (const float*)d_in[8];
  const float* g1     = (const float*)d_in[9];
  const float* be1    = (const float*)d_in[10];
  const float* m1     = (const float*)d_in[11];
  const float* v1     = (const float*)d_in[12];
  const float* w2     = (const float*)d_in[13];
  const float* b2     = (const float*)d_in[14];
  const float* g2     = (const float*)d_in[15];
  const float* be2    = (const float*)d_in[16];
  const float* m2     = (const float*)d_in[17];
  const float* v2     = (const float*)d_in[18];
  const float* taus   = (const float*)d_in[19];
  float* out = (float*)d_out;
  (void)in_sizes; (void)n_in;

  cudaFuncSetAttribute(k_expert, cudaFuncAttributeMaxDynamicSharedMemorySize, XS_BYTES);

  // kernel 1: 256 colmax blocks + 8 prep blocks + 1536 LIF blocks (all independent)
  k_prepall<<<264 + (Bn*Cn)/8, 256>>>(x, w1, g1, be1, m1, v1, b1,
                                      g2, be2, m2, v2, b2, taus);
  float* auxp = (out_size > OUT_MAIN) ? (out + OUT_MAIN) : nullptr;
  // kernel 2: 512 worker blocks (4 per token) + 1 aux block
  k_expert<<<Nn*4 + 1, TPB, XS_BYTES>>>(x, rw, rb, rgam, rbeta, rmean, rvar,
                                        taus, w1, b1, g1, be1, m1, v1, w2,
                                        out, auxp);
}

// round 9
// speedup vs baseline: 2.0267x; 1.0951x over previous
#include <cuda_runtime.h>
#include <math.h>

#define Tn   4
#define Bn   32
#define Cn   384
#define HFn  1536
#define HWn  196
#define En   8
#define Nn   128
#define OUT_MAIN (Nn*Cn*HWn)
#define NG   32
#define GSZ  48
#define NR   12
#define FULLMASK 0xffffffffu

#define PB   28                  // pixels per worker block (7 per token)
#define PBS  29                  // smem row stride (odd -> no bank conflicts)
#define TPB  224                 // 7 warps; each warp owns 4 pixels
#define XS_ELEMS (Cn*PBS)        // 11136 floats
#define MSK_OFF  XS_ELEMS        // per-warp mask scratch: [7][NR]
#define SM_FLOATS (XS_ELEMS + 7*NR)
#define SM_BYTES  (SM_FLOATS*4)  // ~44.9 KB

// ---------------- device scratch ----------------
__device__ float    g_colmax32[En*Cn*NG];  // [e][c][g]
__device__ float    g_thrmin32[En*NG];
__device__ float    g_thrall[En];
__device__ unsigned g_maxcm_u[En];         // zero-init; monotone-key atomicMax (idempotent)
__device__ float    g_xmin[En];            // exact: x >= xmin  <=>  (x/tau - 1) >= 0
__device__ float    g_m2c[En*Cn];
__device__ float    g_a2c[En*Cn];
__device__ float    g_sbar[Nn*Cn];

__device__ __forceinline__ unsigned fkey(float f){
  unsigned b = __float_as_uint(f);
  return (b & 0x80000000u) ? ~b : (b | 0x80000000u);
}
__device__ __forceinline__ float funkey(unsigned k){
  unsigned b = (k & 0x80000000u) ? (k & 0x7fffffffu) : ~k;
  return __uint_as_float(b);
}

// ============ kernel 1: heterogeneous prep (colmax | thresholds | LIF) ============
__global__ void __launch_bounds__(256) k_prepall(
    const float* __restrict__ x,  const float* __restrict__ w1,
    const float* __restrict__ g1, const float* __restrict__ be1,
    const float* __restrict__ m1, const float* __restrict__ v1,
    const float* __restrict__ b1,
    const float* __restrict__ g2, const float* __restrict__ be2,
    const float* __restrict__ m2, const float* __restrict__ v2,
    const float* __restrict__ b2,
    const float* __restrict__ taus){
  int b = blockIdx.x;
  int tid = threadIdx.x, lane = tid & 31;

  if (b < 256){
    int e = b >> 5, g = b & 31;
    float lmax = -1e30f;
    for (int c = tid; c < Cn; c += 256){
      const float* base = w1 + ((size_t)e*HFn + g*GSZ)*Cn + c;
      float m = -1e30f;
      #pragma unroll 8
      for (int o=0;o<GSZ;o++) m = fmaxf(m, base[(size_t)o*Cn]);
      g_colmax32[((size_t)e*Cn + c)*NG + g] = m;
      lmax = fmaxf(lmax, m);
    }
    #pragma unroll
    for (int d=16;d>=1;d>>=1) lmax = fmaxf(lmax, __shfl_xor_sync(FULLMASK, lmax, d));
    if (lane==0) atomicMax(&g_maxcm_u[e], fkey(lmax));
    return;
  }

  if (b < 264){
    int e = b - 256;
    __shared__ float s_thr[HFn];
    float tau = taus[e];
    for (int o = tid; o < HFn; o += 256){
      float iv = g1[e*HFn+o] * rsqrtf(v1[e*HFn+o] + 1e-5f);
      float sh = be1[e*HFn+o] - m1[e*HFn+o]*iv;
      s_thr[o] = (iv > 0.0f) ? ((tau - sh)/iv - b1[e*HFn+o]) : -1e30f;
    }
    for (int c = tid; c < Cn; c += 256){
      float inv = g2[e*Cn+c] * rsqrtf(v2[e*Cn+c] + 1e-5f);
      float sh  = be2[e*Cn+c] - m2[e*Cn+c]*inv;
      g_m2c[e*Cn+c] = inv;
      g_a2c[e*Cn+c] = inv*b2[e*Cn+c] + sh;
    }
    __syncthreads();
    if (tid < NG){
      float mn = 1e30f;
      #pragma unroll 8
      for (int i=0;i<GSZ;i++) mn = fminf(mn, s_thr[tid*GSZ + i]);
      g_thrmin32[e*NG + tid] = mn;
      float ta = mn;
      #pragma unroll
      for (int d=16;d>=1;d>>=1) ta = fminf(ta, __shfl_xor_sync(FULLMASK, ta, d));
      if (tid==0) g_thrall[e] = ta;
    }
    if (tid==64){
      float y = tau;                       // tau/tau == 1 exactly
      for (int it=0; it<8; it++){
        float z = nextafterf(y, 0.0f);
        if ((z/tau - 1.0f) >= 0.0f) y = z; else break;
      }
      g_xmin[e] = y;
    }
    return;
  }

  {
    int w = (b - 264)*8 + (tid >> 5);      // 0..12287 = bidx*Cn + c
    int bi = w / Cn, c = w - bi*Cn;
    const float* xb = x + ((size_t)bi*Cn + c)*HWn;
    float v[7] = {0.f,0.f,0.f,0.f,0.f,0.f,0.f};
    #pragma unroll
    for (int t=0;t<Tn;t++){
      const float* xt = xb + (size_t)t*Bn*Cn*HWn;
      int cntl = 0;
      #pragma unroll
      for (int k=0;k<7;k++){
        int p = lane + k*32;
        if (p < HWn){
          float xv = xt[p];
          v[k] += (xv - v[k])*0.5f;
          bool s = (v[k] - 1.0f) >= 0.0f;
          cntl += s ? 1 : 0;
          if (s) v[k] = 0.0f;
        }
      }
      int cnt = __reduce_add_sync(FULLMASK, cntl);
      if (lane==0) g_sbar[(t*Bn+bi)*Cn + c] = (float)cnt / (float)HWn;
    }
  }
}

// ---------------- inline gate (identical code for workers and aux) ----------------
__device__ __forceinline__ void gate_compute(
    int n, int lane,
    const float* __restrict__ rw, const float* __restrict__ rb,
    const float* __restrict__ rg, const float* __restrict__ rbeta,
    const float* __restrict__ rmean, const float* __restrict__ rvar,
    int& i1o, int& i2o, float& g1o, float& g2o, float* probs){
  float sv[NR];
  #pragma unroll
  for (int r=0;r<NR;r++) sv[r] = g_sbar[n*Cn + r*32 + lane];
  float lg[En];
  #pragma unroll
  for (int e=0;e<En;e++){
    float v = 0.0f;
    #pragma unroll
    for (int r=0;r<NR;r++) v += sv[r] * rw[e*Cn + r*32 + lane];
    #pragma unroll
    for (int d=16;d>=1;d>>=1) v += __shfl_xor_sync(FULLMASK, v, d);
    float inv = rg[e] * rsqrtf(rvar[e] + 1e-5f);
    lg[e] = inv*(v + rb[e]) + (rbeta[e] - rmean[e]*inv);
  }
  float mx = lg[0];
  #pragma unroll
  for (int e=1;e<En;e++) mx = fmaxf(mx, lg[e]);
  float pe[En]; float sum = 0.0f;
  #pragma unroll
  for (int e=0;e<En;e++){ pe[e] = expf(lg[e]-mx); sum += pe[e]; }
  #pragma unroll
  for (int e=0;e<En;e++) pe[e] /= sum;
  int i1 = 0; float p1 = pe[0];
  #pragma unroll
  for (int e=1;e<En;e++) if (pe[e] > p1){ p1 = pe[e]; i1 = e; }
  int i2 = -1; float p2 = -1.0f;
  #pragma unroll
  for (int e=0;e<En;e++) if (e != i1 && pe[e] > p2){ p2 = pe[e]; i2 = e; }
  float ws = p1 + p2;
  i1o = i1; i2o = i2; g1o = p1/ws; g2o = p2/ws;
  if (probs){
    #pragma unroll
    for (int e=0;e<En;e++) probs[e] = pe[e];
  }
}

// ============ kernel 2: expert (smem-staged) + aux as block 0 ============
extern __shared__ float xs[];   // [Cn][PBS] tile + [7][NR] mask scratch

__global__ void __launch_bounds__(TPB, 4) k_expert(
    const float* __restrict__ x,
    const float* __restrict__ rw, const float* __restrict__ rb,
    const float* __restrict__ rg, const float* __restrict__ rbeta,
    const float* __restrict__ rmean, const float* __restrict__ rvar,
    const float* __restrict__ taus,
    const float* __restrict__ w1, const float* __restrict__ b1,
    const float* __restrict__ g1, const float* __restrict__ be1,
    const float* __restrict__ m1, const float* __restrict__ v1,
    const float* __restrict__ w2,
    float* __restrict__ out, float* __restrict__ auxout){
  int b = blockIdx.x;
  int tid = threadIdx.x, lane = tid & 31, w = tid >> 5;

  if (b == 0){
    // ---- aux block (runs in wave 1, overlapped with workers) ----
    float* fs = xs;        // [7][8]
    float* ps = xs + 64;   // [7][8]
    float facc[En], pacc[En];
    #pragma unroll
    for (int e=0;e<En;e++){ facc[e]=0.f; pacc[e]=0.f; }
    for (int n = w; n < Nn; n += 7){
      int i1,i2; float a,bb; float pe[En];
      gate_compute(n, lane, rw, rb, rg, rbeta, rmean, rvar, i1, i2, a, bb, pe);
      #pragma unroll
      for (int e=0;e<En;e++){
        facc[e] += (i1==e || i2==e) ? 1.0f : 0.0f;
        pacc[e] += pe[e];
      }
    }
    if (lane==0){
      #pragma unroll
      for (int e=0;e<En;e++){ fs[w*8+e] = facc[e]; ps[w*8+e] = pacc[e]; }
    }
    __syncthreads();
    if (tid==0 && auxout){
      float s = 0.0f;
      #pragma unroll
      for (int e=0;e<En;e++){
        float fe = 0.f, pp = 0.f;
        #pragma unroll
        for (int q=0;q<7;q++){ fe += fs[q*8+e]; pp += ps[q*8+e]; }
        s += (fe/(float)Nn) * (pp/(float)Nn);
      }
      auxout[0] = 0.01f * (float)En * s;
    }
    return;
  }

  int wb = b - 1;
  int n = wb / 7;
  int pbase = (wb - n*7) * PB;
  unsigned* msks = (unsigned*)(xs + MSK_OFF) + w*NR;

  // ---- cooperative coalesced load of the x tile [384][28] (stride 29) ----
  const float* xrow = x + (size_t)n*Cn*HWn + pbase;
  for (int i = tid; i < Cn*PB; i += TPB){
    int c = i / PB, p = i - c*PB;
    xs[c*PBS + p] = xrow[(size_t)c*HWn + p];
  }

  // ---- per-warp gate ----
  int e0, e1; float gw0, gw1;
  gate_compute(n, lane, rw, rb, rg, rbeta, rmean, rvar, e0, e1, gw0, gw1, (float*)0);

  float tau0 = taus[e0],  tau1 = taus[e1];
  float xm0  = g_xmin[e0], xm1 = g_xmin[e1];
  float thr0 = g_thrall[e0] - 1e-3f, thr1 = g_thrall[e1] - 1e-3f;
  float mc0  = funkey(g_maxcm_u[e0]), mc1 = funkey(g_maxcm_u[e1]);

  __syncthreads();

  // ---- compute: warp w owns smem columns 4w..4w+3; no barriers until the end ----
  for (int j=0;j<4;j++){
    int col = w*4 + j;
    float xv[NR];
    #pragma unroll
    for (int r=0;r<NR;r++) xv[r] = xs[(r*32+lane)*PBS + col];

    // both experts' lane-local spike masks BEFORE xv becomes the accumulator
    unsigned lmA = 0, lmB = 0;
    #pragma unroll
    for (int r=0;r<NR;r++){
      lmA |= (xv[r] >= xm0) ? (1u << r) : 0u;
      lmB |= (xv[r] >= xm1) ? (1u << r) : 0u;
    }
    #pragma unroll
    for (int r=0;r<NR;r++) xv[r] *= (gw0 + gw1);   // residual; xv is now the result accum

    #pragma unroll
    for (int k=0;k<2;k++){
      int   e   = k ? e1   : e0;
      float gw  = k ? gw1  : gw0;
      float tau = k ? tau1 : tau0;
      float thr = k ? thr1 : thr0;
      float mc  = k ? mc1  : mc0;
      unsigned lm = k ? lmB : lmA;
      const float* a2 = g_a2c + e*Cn + lane;

      int cnt = __reduce_add_sync(FULLMASK, __popc(lm));

      if ((float)cnt * mc < thr){
        #pragma unroll
        for (int r=0;r<NR;r++) xv[r] += gw * a2[r*32];
        continue;
      }

      // masks to per-warp smem (only on the non-light path)
      #pragma unroll
      for (int r=0;r<NR;r++){
        unsigned m = __ballot_sync(FULLMASK, (lm >> r) & 1u);
        if (lane == 0) msks[r] = m;
      }
      __syncwarp();

      // tier 2: per-group bound; lane = group g
      float ub;
      {
        const float* cmB = g_colmax32 + (size_t)e*Cn*NG + lane;
        float pr[4] = {0.f,0.f,0.f,0.f};
        #pragma unroll
        for (int r=0;r<NR;r++){
          unsigned mm = msks[r];
          float pp = 0.0f;
          while (mm){
            int bb = __ffs(mm)-1; mm &= mm-1;
            pp += cmB[(size_t)(r*32 + bb)*NG];
          }
          pr[r & 3] += pp;
        }
        ub = (pr[0]+pr[1]) + (pr[2]+pr[3]);
      }
      bool fail = ub >= g_thrmin32[e*NG + lane] - 1e-3f;
      unsigned fm = __ballot_sync(FULLMASK, fail);
      if (fm == 0){
        #pragma unroll
        for (int r=0;r<NR;r++) xv[r] += gw * a2[r*32];
        continue;
      }

      // tier 3: exact for failing groups (rare)
      float a[NR];
      #pragma unroll
      for (int r=0;r<NR;r++) a[r] = 0.0f;
      int nf = 0;
      while (fm){
        int g = __ffs(fm)-1; fm &= fm-1;
        float h0 = 0.0f, h1 = 0.0f;
        const float* w1b  = w1 + ((size_t)e*HFn + g*GSZ)*Cn;
        const float* w1r0 = w1b + (size_t)lane*Cn;
        const float* w1r1 = w1b + (size_t)(32+lane)*Cn;
        #pragma unroll
        for (int r=0;r<NR;r++){
          unsigned mm = msks[r];
          while (mm){
            int bb = __ffs(mm)-1; mm &= mm-1;
            int c = r*32 + bb;
            h0 += w1r0[c];
            if (lane < 16) h1 += w1r1[c];
          }
        }
        int o0 = g*GSZ + lane;
        float iv0 = g1[e*HFn+o0] * rsqrtf(v1[e*HFn+o0] + 1e-5f);
        float q0  = iv0*b1[e*HFn+o0] + (be1[e*HFn+o0] - m1[e*HFn+o0]*iv0) - tau;
        bool f0 = fmaf(iv0, h0, q0) >= 0.0f;
        bool f1 = false;
        if (lane < 16){
          int o1 = g*GSZ + 32 + lane;
          float iv1 = g1[e*HFn+o1] * rsqrtf(v1[e*HFn+o1] + 1e-5f);
          float q1  = iv1*b1[e*HFn+o1] + (be1[e*HFn+o1] - m1[e*HFn+o1]*iv1) - tau;
          f1 = fmaf(iv1, h1, q1) >= 0.0f;
        }
        unsigned fa0 = __ballot_sync(FULLMASK, f0);
        unsigned fa1 = __ballot_sync(FULLMASK, f1);
        unsigned t = fa0;
        while (t){
          int bb = __ffs(t)-1; t &= t-1;
          const float* w2b = w2 + ((size_t)e*Cn + lane)*HFn + (g*GSZ + bb);
          #pragma unroll
          for (int r=0;r<NR;r++) a[r] += w2b[(size_t)r*32*HFn];
          nf++;
        }
        t = fa1;
        while (t){
          int bb = __ffs(t)-1; t &= t-1;
          const float* w2b = w2 + ((size_t)e*Cn + lane)*HFn + (g*GSZ + 32 + bb);
          #pragma unroll
          for (int r=0;r<NR;r++) a[r] += w2b[(size_t)r*32*HFn];
          nf++;
        }
      }
      if (nf){
        #pragma unroll
        for (int r=0;r<NR;r++){
          float inv2 = g_m2c[e*Cn + r*32 + lane];
          xv[r] += gw * fmaf(inv2, a[r], a2[r*32]);
        }
      } else {
        #pragma unroll
        for (int r=0;r<NR;r++) xv[r] += gw * a2[r*32];
      }
    }

    #pragma unroll
    for (int r=0;r<NR;r++) xs[(r*32+lane)*PBS + col] = xv[r];
  }

  __syncthreads();

  // ---- cooperative coalesced store ----
  float* orow = out + (size_t)n*Cn*HWn + pbase;
  for (int i = tid; i < Cn*PB; i += TPB){
    int c = i / PB, p = i - c*PB;
    orow[(size_t)c*HWn + p] = xs[c*PBS + p];
  }
}

// ---------------- launch ----------------
extern "C" void kernel_launch(void* const* d_in, const int* in_sizes, int n_in,
                              void* d_out, int out_size){
  const float* x      = (const float*)d_in[0];
  const float* rw     = (const float*)d_in[1];
  const float* rb     = (const float*)d_in[2];
  const float* rgam   = (const float*)d_in[3];
  const float* rbeta  = (const float*)d_in[4];
  const float* rmean  = (const float*)d_in[5];
  const float* rvar   = (const float*)d_in[6];
  const float* w1     = (const float*)d_in[7];
  const float* b1     = (const float*)d_in[8];
  const float* g1     = (const float*)d_in[9];
  const float* be1    = (const float*)d_in[10];
  const float* m1     = (const float*)d_in[11];
  const float* v1     = (const float*)d_in[12];
  const float* w2     = (const float*)d_in[13];
  const float* b2     = (const float*)d_in[14];
  const float* g2     = (const float*)d_in[15];
  const float* be2    = (const float*)d_in[16];
  const float* m2     = (const float*)d_in[17];
  const float* v2     = (const float*)d_in[18];
  const float* taus   = (const float*)d_in[19];
  float* out = (float*)d_out;
  (void)in_sizes; (void)n_in;

  cudaFuncSetAttribute(k_expert, cudaFuncAttributeMaxDynamicSharedMemorySize, SM_BYTES);

  k_prepall<<<264 + (Bn*Cn)/8, 256>>>(x, w1, g1, be1, m1, v1, b1,
                                      g2, be2, m2, v2, b2, taus);
  float* auxp = (out_size > OUT_MAIN) ? (out + OUT_MAIN) : nullptr;
  // block 0 = aux; blocks 1..896 = workers (7 per token)
  k_expert<<<1 + Nn*7, TPB, SM_BYTES>>>(x, rw, rb, rgam, rbeta, rmean, rvar,
                                        taus, w1, b1, g1, be1, m1, v1, w2,
                                        out, auxp);
}

// round 10
// speedup vs baseline: 2.1743x; 1.0728x over previous
#include <cuda_runtime.h>
#include <math.h>

#define Tn   4
#define Bn   32
#define Cn   384
#define HFn  1536
#define HWn  196
#define En   8
#define Nn   128
#define OUT_MAIN (Nn*Cn*HWn)
#define NG   32
#define GSZ  48
#define NR   12
#define FULLMASK 0xffffffffu

#define PB   28                  // pixels per worker block (7 per token)
#define PBS  29                  // smem row stride (odd -> bank-conflict-free)
#define TPB  224                 // 7 warps; each warp owns 4 pixels
#define XS_ELEMS (Cn*PBS)        // 11136 floats
#define COMB_OFF XS_ELEMS        // comb[384]
#define GATE_OFF (COMB_OFF+Cn)   // e0,e1,gw0,gw1
#define MSK_OFF  (GATE_OFF+4)    // [7][NR] unsigned
#define SM_FLOATS (MSK_OFF + 7*NR)
#define SM_BYTES  (SM_FLOATS*4)  // ~46.4 KB

// ---------------- device scratch ----------------
__device__ float    g_colmax32[En*Cn*NG];  // [e][c][g]
__device__ float    g_thrmin32[En*NG];
__device__ float    g_thrall[En];
__device__ unsigned g_maxcm_u[En];         // zero-init; monotone-key atomicMax (idempotent)
__device__ float    g_xmin[En];            // exact: x >= xmin  <=>  (x/tau - 1) >= 0
__device__ float    g_m2c[En*Cn];
__device__ float    g_a2c[En*Cn];
__device__ float    g_sbar[Nn*Cn];

__device__ __forceinline__ unsigned fkey(float f){
  unsigned b = __float_as_uint(f);
  return (b & 0x80000000u) ? ~b : (b | 0x80000000u);
}
__device__ __forceinline__ float funkey(unsigned k){
  unsigned b = (k & 0x80000000u) ? (k & 0x7fffffffu) : ~k;
  return __uint_as_float(b);
}

// ============ kernel 1: heterogeneous prep (colmax | thresholds | LIF) ============
__global__ void __launch_bounds__(256) k_prepall(
    const float* __restrict__ x,  const float* __restrict__ w1,
    const float* __restrict__ g1, const float* __restrict__ be1,
    const float* __restrict__ m1, const float* __restrict__ v1,
    const float* __restrict__ b1,
    const float* __restrict__ g2, const float* __restrict__ be2,
    const float* __restrict__ m2, const float* __restrict__ v2,
    const float* __restrict__ b2,
    const float* __restrict__ taus){
  int b = blockIdx.x;
  int tid = threadIdx.x, lane = tid & 31;

  if (b < 256){
    int e = b >> 5, g = b & 31;
    float lmax = -1e30f;
    for (int c = tid; c < Cn; c += 256){
      const float* base = w1 + ((size_t)e*HFn + g*GSZ)*Cn + c;
      float m = -1e30f;
      #pragma unroll 8
      for (int o=0;o<GSZ;o++) m = fmaxf(m, base[(size_t)o*Cn]);
      g_colmax32[((size_t)e*Cn + c)*NG + g] = m;
      lmax = fmaxf(lmax, m);
    }
    #pragma unroll
    for (int d=16;d>=1;d>>=1) lmax = fmaxf(lmax, __shfl_xor_sync(FULLMASK, lmax, d));
    if (lane==0) atomicMax(&g_maxcm_u[e], fkey(lmax));
    return;
  }

  if (b < 264){
    int e = b - 256;
    __shared__ float s_thr[HFn];
    float tau = taus[e];
    for (int o = tid; o < HFn; o += 256){
      float iv = g1[e*HFn+o] * rsqrtf(v1[e*HFn+o] + 1e-5f);
      float sh = be1[e*HFn+o] - m1[e*HFn+o]*iv;
      s_thr[o] = (iv > 0.0f) ? ((tau - sh)/iv - b1[e*HFn+o]) : -1e30f;
    }
    for (int c = tid; c < Cn; c += 256){
      float inv = g2[e*Cn+c] * rsqrtf(v2[e*Cn+c] + 1e-5f);
      float sh  = be2[e*Cn+c] - m2[e*Cn+c]*inv;
      g_m2c[e*Cn+c] = inv;
      g_a2c[e*Cn+c] = inv*b2[e*Cn+c] + sh;
    }
    __syncthreads();
    if (tid < NG){
      float mn = 1e30f;
      #pragma unroll 8
      for (int i=0;i<GSZ;i++) mn = fminf(mn, s_thr[tid*GSZ + i]);
      g_thrmin32[e*NG + tid] = mn;
      float ta = mn;
      #pragma unroll
      for (int d=16;d>=1;d>>=1) ta = fminf(ta, __shfl_xor_sync(FULLMASK, ta, d));
      if (tid==0) g_thrall[e] = ta;
    }
    if (tid==64){
      float y = tau;                       // tau/tau == 1 exactly
      for (int it=0; it<8; it++){
        float z = nextafterf(y, 0.0f);
        if ((z/tau - 1.0f) >= 0.0f) y = z; else break;
      }
      g_xmin[e] = y;
    }
    return;
  }

  {
    int w = (b - 264)*8 + (tid >> 5);      // 0..12287 = bidx*Cn + c
    int bi = w / Cn, c = w - bi*Cn;
    const float* xb = x + ((size_t)bi*Cn + c)*HWn;
    float v[7] = {0.f,0.f,0.f,0.f,0.f,0.f,0.f};
    #pragma unroll
    for (int t=0;t<Tn;t++){
      const float* xt = xb + (size_t)t*Bn*Cn*HWn;
      int cntl = 0;
      #pragma unroll
      for (int k=0;k<7;k++){
        int p = lane + k*32;
        if (p < HWn){
          float xv = xt[p];
          v[k] += (xv - v[k])*0.5f;
          bool s = (v[k] - 1.0f) >= 0.0f;
          cntl += s ? 1 : 0;
          if (s) v[k] = 0.0f;
        }
      }
      int cnt = __reduce_add_sync(FULLMASK, cntl);
      if (lane==0) g_sbar[(t*Bn+bi)*Cn + c] = (float)cnt / (float)HWn;
    }
  }
}

// ---------------- inline gate (identical code for workers and aux) ----------------
__device__ __forceinline__ void gate_compute(
    int n, int lane,
    const float* __restrict__ rw, const float* __restrict__ rb,
    const float* __restrict__ rg, const float* __restrict__ rbeta,
    const float* __restrict__ rmean, const float* __restrict__ rvar,
    int& i1o, int& i2o, float& g1o, float& g2o, float* probs){
  float sv[NR];
  #pragma unroll
  for (int r=0;r<NR;r++) sv[r] = g_sbar[n*Cn + r*32 + lane];
  float lg[En];
  #pragma unroll
  for (int e=0;e<En;e++){
    float v = 0.0f;
    #pragma unroll
    for (int r=0;r<NR;r++) v += sv[r] * rw[e*Cn + r*32 + lane];
    #pragma unroll
    for (int d=16;d>=1;d>>=1) v += __shfl_xor_sync(FULLMASK, v, d);
    float inv = rg[e] * rsqrtf(rvar[e] + 1e-5f);
    lg[e] = inv*(v + rb[e]) + (rbeta[e] - rmean[e]*inv);
  }
  float mx = lg[0];
  #pragma unroll
  for (int e=1;e<En;e++) mx = fmaxf(mx, lg[e]);
  float pe[En]; float sum = 0.0f;
  #pragma unroll
  for (int e=0;e<En;e++){ pe[e] = expf(lg[e]-mx); sum += pe[e]; }
  #pragma unroll
  for (int e=0;e<En;e++) pe[e] /= sum;
  int i1 = 0; float p1 = pe[0];
  #pragma unroll
  for (int e=1;e<En;e++) if (pe[e] > p1){ p1 = pe[e]; i1 = e; }
  int i2 = -1; float p2 = -1.0f;
  #pragma unroll
  for (int e=0;e<En;e++) if (e != i1 && pe[e] > p2){ p2 = pe[e]; i2 = e; }
  float ws = p1 + p2;
  i1o = i1; i2o = i2; g1o = p1/ws; g2o = p2/ws;
  if (probs){
    #pragma unroll
    for (int e=0;e<En;e++) probs[e] = pe[e];
  }
}

// ============ kernel 2: expert (smem-staged, comb-folded) + aux as block 0 ============
extern __shared__ float xs[];

__global__ void __launch_bounds__(TPB, 4) k_expert(
    const float* __restrict__ x,
    const float* __restrict__ rw, const float* __restrict__ rb,
    const float* __restrict__ rg, const float* __restrict__ rbeta,
    const float* __restrict__ rmean, const float* __restrict__ rvar,
    const float* __restrict__ taus,
    const float* __restrict__ w1, const float* __restrict__ b1,
    const float* __restrict__ g1, const float* __restrict__ be1,
    const float* __restrict__ m1, const float* __restrict__ v1,
    const float* __restrict__ w2,
    float* __restrict__ out, float* __restrict__ auxout){
  int b = blockIdx.x;
  int tid = threadIdx.x, lane = tid & 31, w = tid >> 5;

  if (b == 0){
    // ---- aux block (wave 1, overlapped with workers) ----
    float* fs = xs;        // [7][8]
    float* ps = xs + 64;   // [7][8]
    float facc[En], pacc[En];
    #pragma unroll
    for (int e=0;e<En;e++){ facc[e]=0.f; pacc[e]=0.f; }
    for (int n = w; n < Nn; n += 7){
      int i1,i2; float a,bb; float pe[En];
      gate_compute(n, lane, rw, rb, rg, rbeta, rmean, rvar, i1, i2, a, bb, pe);
      #pragma unroll
      for (int e=0;e<En;e++){
        facc[e] += (i1==e || i2==e) ? 1.0f : 0.0f;
        pacc[e] += pe[e];
      }
    }
    if (lane==0){
      #pragma unroll
      for (int e=0;e<En;e++){ fs[w*8+e] = facc[e]; ps[w*8+e] = pacc[e]; }
    }
    __syncthreads();
    if (tid==0 && auxout){
      float s = 0.0f;
      #pragma unroll
      for (int e=0;e<En;e++){
        float fe = 0.f, pp = 0.f;
        #pragma unroll
        for (int q=0;q<7;q++){ fe += fs[q*8+e]; pp += ps[q*8+e]; }
        s += (fe/(float)Nn) * (pp/(float)Nn);
      }
      auxout[0] = 0.01f * (float)En * s;
    }
    return;
  }

  int wb = b - 1;
  int n = wb / 7;
  int pbase = (wb - n*7) * PB;
  float* comb = xs + COMB_OFF;
  float* gsh  = xs + GATE_OFF;
  unsigned* msks = (unsigned*)(xs + MSK_OFF) + w*NR;

  // ---- cooperative coalesced load of the x tile [384][28] (stride 29) ----
  const float* xrow = x + (size_t)n*Cn*HWn + pbase;
  for (int i = tid; i < Cn*PB; i += TPB){
    int c = i / PB, p = i - c*PB;
    xs[c*PBS + p] = xrow[(size_t)c*HWn + p];
  }

  // ---- gate once per block (warp 0), overlapped with in-flight tile loads ----
  if (w == 0){
    int e0_, e1_; float gw0_, gw1_;
    gate_compute(n, lane, rw, rb, rg, rbeta, rmean, rvar, e0_, e1_, gw0_, gw1_, (float*)0);
    if (lane == 0){
      gsh[0] = __int_as_float(e0_); gsh[1] = __int_as_float(e1_);
      gsh[2] = gw0_; gsh[3] = gw1_;
    }
  }
  __syncthreads();

  int   e0  = __float_as_int(gsh[0]), e1 = __float_as_int(gsh[1]);
  float gw0 = gsh[2], gw1 = gsh[3];

  // ---- comb[c] = gw0*a2[e0][c] + gw1*a2[e1][c]  (covers both light contributions) ----
  for (int c = tid; c < Cn; c += TPB)
    comb[c] = gw0*g_a2c[e0*Cn+c] + gw1*g_a2c[e1*Cn+c];

  float gws  = gw0 + gw1;
  float xm0  = g_xmin[e0], xm1 = g_xmin[e1];
  float thr0 = g_thrall[e0] - 1e-3f, thr1 = g_thrall[e1] - 1e-3f;
  float mc0  = funkey(g_maxcm_u[e0]), mc1 = funkey(g_maxcm_u[e1]);
  float tau0 = taus[e0], tau1 = taus[e1];

  __syncthreads();

  // ---- compute: warp w owns smem columns 4w..4w+3; no block barriers here ----
  for (int j=0;j<4;j++){
    int col = w*4 + j;
    float xv[NR];
    #pragma unroll
    for (int r=0;r<NR;r++) xv[r] = xs[(r*32+lane)*PBS + col];

    unsigned lmA = 0, lmB = 0;
    #pragma unroll
    for (int r=0;r<NR;r++){
      lmA |= (xv[r] >= xm0) ? (1u << r) : 0u;
      lmB |= (xv[r] >= xm1) ? (1u << r) : 0u;
    }
    // residual + both experts' BN-bias terms in one pass
    #pragma unroll
    for (int r=0;r<NR;r++) xv[r] = fmaf(xv[r], gws, comb[r*32+lane]);

    // packed dual count, one reduce
    int pk = __popc(lmA) | (__popc(lmB) << 16);
    int sums = __reduce_add_sync(FULLMASK, pk);
    int cntA = sums & 0xffff, cntB = sums >> 16;

    bool lightA = (float)cntA * mc0 < thr0;
    bool lightB = (float)cntB * mc1 < thr1;
    if (!(lightA && lightB)){
      #pragma unroll
      for (int k=0;k<2;k++){
        if (k ? lightB : lightA) continue;
        int   e   = k ? e1   : e0;
        float gw  = k ? gw1  : gw0;
        float tau = k ? tau1 : tau0;
        unsigned lm = k ? lmB : lmA;

        #pragma unroll
        for (int r=0;r<NR;r++){
          unsigned m = __ballot_sync(FULLMASK, (lm >> r) & 1u);
          if (lane == 0) msks[r] = m;
        }
        __syncwarp();

        // tier 2: per-group bound; lane = group g
        float ub;
        {
          const float* cmB = g_colmax32 + (size_t)e*Cn*NG + lane;
          float pr[4] = {0.f,0.f,0.f,0.f};
          #pragma unroll
          for (int r=0;r<NR;r++){
            unsigned mm = msks[r];
            float pp = 0.0f;
            while (mm){
              int bb = __ffs(mm)-1; mm &= mm-1;
              pp += cmB[(size_t)(r*32 + bb)*NG];
            }
            pr[r & 3] += pp;
          }
          ub = (pr[0]+pr[1]) + (pr[2]+pr[3]);
        }
        bool fail = ub >= g_thrmin32[e*NG + lane] - 1e-3f;
        unsigned fm = __ballot_sync(FULLMASK, fail);
        if (fm == 0) continue;                    // comb already covers this expert

        // tier 3: exact for failing groups (rare)
        float a[NR];
        #pragma unroll
        for (int r=0;r<NR;r++) a[r] = 0.0f;
        int nf = 0;
        while (fm){
          int g = __ffs(fm)-1; fm &= fm-1;
          float h0 = 0.0f, h1 = 0.0f;
          const float* w1b  = w1 + ((size_t)e*HFn + g*GSZ)*Cn;
          const float* w1r0 = w1b + (size_t)lane*Cn;
          const float* w1r1 = w1b + (size_t)(32+lane)*Cn;
          #pragma unroll
          for (int r=0;r<NR;r++){
            unsigned mm = msks[r];
            while (mm){
              int bb = __ffs(mm)-1; mm &= mm-1;
              int c = r*32 + bb;
              h0 += w1r0[c];
              if (lane < 16) h1 += w1r1[c];
            }
          }
          int o0 = g*GSZ + lane;
          float iv0 = g1[e*HFn+o0] * rsqrtf(v1[e*HFn+o0] + 1e-5f);
          float q0  = iv0*b1[e*HFn+o0] + (be1[e*HFn+o0] - m1[e*HFn+o0]*iv0) - tau;
          bool f0 = fmaf(iv0, h0, q0) >= 0.0f;
          bool f1 = false;
          if (lane < 16){
            int o1 = g*GSZ + 32 + lane;
            float iv1 = g1[e*HFn+o1] * rsqrtf(v1[e*HFn+o1] + 1e-5f);
            float q1  = iv1*b1[e*HFn+o1] + (be1[e*HFn+o1] - m1[e*HFn+o1]*iv1) - tau;
            f1 = fmaf(iv1, h1, q1) >= 0.0f;
          }
          unsigned fa0 = __ballot_sync(FULLMASK, f0);
          unsigned fa1 = __ballot_sync(FULLMASK, f1);
          unsigned t = fa0;
          while (t){
            int bb = __ffs(t)-1; t &= t-1;
            const float* w2b = w2 + ((size_t)e*Cn + lane)*HFn + (g*GSZ + bb);
            #pragma unroll
            for (int r=0;r<NR;r++) a[r] += w2b[(size_t)r*32*HFn];
            nf++;
          }
          t = fa1;
          while (t){
            int bb = __ffs(t)-1; t &= t-1;
            const float* w2b = w2 + ((size_t)e*Cn + lane)*HFn + (g*GSZ + 32 + bb);
            #pragma unroll
            for (int r=0;r<NR;r++) a[r] += w2b[(size_t)r*32*HFn];
            nf++;
          }
        }
        if (nf){
          // comb carries gw*a2; heavy correction is gw*inv2*a only
          #pragma unroll
          for (int r=0;r<NR;r++){
            float inv2 = g_m2c[e*Cn + r*32 + lane];
            xv[r] += gw * (inv2 * a[r]);
          }
        }
      }
    }

    #pragma unroll
    for (int r=0;r<NR;r++) xs[(r*32+lane)*PBS + col] = xv[r];
  }

  __syncthreads();

  // ---- cooperative coalesced store ----
  float* orow = out + (size_t)n*Cn*HWn + pbase;
  for (int i = tid; i < Cn*PB; i += TPB){
    int c = i / PB, p = i - c*PB;
    orow[(size_t)c*HWn + p] = xs[c*PBS + p];
  }
}

// ---------------- launch ----------------
extern "C" void kernel_launch(void* const* d_in, const int* in_sizes, int n_in,
                              void* d_out, int out_size){
  const float* x      = (const float*)d_in[0];
  const float* rw     = (const float*)d_in[1];
  const float* rb     = (const float*)d_in[2];
  const float* rgam   = (const float*)d_in[3];
  const float* rbeta  = (const float*)d_in[4];
  const float* rmean  = (const float*)d_in[5];
  const float* rvar   = (const float*)d_in[6];
  const float* w1     = (const float*)d_in[7];
  const float* b1     = (const float*)d_in[8];
  const float* g1     = (const float*)d_in[9];
  const float* be1    = (const float*)d_in[10];
  const float* m1     = (const float*)d_in[11];
  const float* v1     = (const float*)d_in[12];
  const float* w2     = (const float*)d_in[13];
  const float* b2     = (const float*)d_in[14];
  const float* g2     = (const float*)d_in[15];
  const float* be2    = (const float*)d_in[16];
  const float* m2     = (const float*)d_in[17];
  const float* v2     = (const float*)d_in[18];
  const float* taus   = (const float*)d_in[19];
  float* out = (float*)d_out;
  (void)in_sizes; (void)n_in;

  cudaFuncSetAttribute(k_expert, cudaFuncAttributeMaxDynamicSharedMemorySize, SM_BYTES);

  k_prepall<<<264 + (Bn*Cn)/8, 256>>>(x, w1, g1, be1, m1, v1, b1,
                                      g2, be2, m2, v2, b2, taus);
  float* auxp = (out_size > OUT_MAIN) ? (out + OUT_MAIN) : nullptr;
  k_expert<<<1 + Nn*7, TPB, SM_BYTES>>>(x, rw, rb, rgam, rbeta, rmean, rvar,
                                        taus, w1, b1, g1, be1, m1, v1, w2,
                                        out, auxp);
}